// round 9
// baseline (speedup 1.0000x reference)
#include <cuda_runtime.h>
#include <cstdint>

#define UNITS        32768
#define ROW_BYTES    4096                  // 1024 uint32 per weight row
#define OUT_WORDS    1024
#define GRID         152                   // persistent: 1 CTA per SM (GB300 = 152 SMs)
#define THREADS      1024                  // 32 warps
#define DEPTH        4                     // pipeline stages
#define ROWS_PER_STAGE 8
#define STAGE_BYTES  (ROWS_PER_STAGE * ROW_BYTES)   // 32 KB
#define STAGES_PER_WORD 4                  // 32 rows / 8

// dynamic smem layout (bytes)
#define SM_IN      0                       // 4096: packed input
#define SM_ACC     4096                    // 32*4*4 = 512: per-(row,seg) partials
#define SM_B       4608                    // up to 7*32*4 = 896: prefetched biases
#define SM_MBAR    5504                    // DEPTH*8 = 32
#define SM_STAGES  8192                    // DEPTH*32KB = 131072
#define SMEM_TOTAL (SM_STAGES + DEPTH * STAGE_BYTES)   // 139264

__device__ __forceinline__ uint32_t s2u(const void* p) {
    uint32_t a;
    asm("{ .reg .u64 t; cvta.to.shared.u64 t, %1; cvt.u32.u64 %0, t; }"
        : "=r"(a) : "l"(p));
    return a;
}

__device__ __forceinline__ void mbar_wait(uint32_t mb, uint32_t phase) {
    asm volatile(
        "{\n\t.reg .pred P1;\n"
        "WAIT_LOOP_%=:\n\t"
        "mbarrier.try_wait.parity.acquire.cta.shared::cta.b64 P1, [%0], %1, 0x989680;\n\t"
        "@P1 bra.uni WAIT_DONE_%=;\n\t"
        "bra.uni WAIT_LOOP_%=;\n"
        "WAIT_DONE_%=:\n\t}"
        :: "r"(mb), "r"(phase) : "memory");
}

__device__ __forceinline__ void issue_stage(uint32_t dst_smem, const char* src,
                                            uint32_t mb) {
    asm volatile("mbarrier.arrive.expect_tx.shared.b64 _, [%0], %1;"
                 :: "r"(mb), "r"((uint32_t)STAGE_BYTES) : "memory");
    asm volatile(
        "cp.async.bulk.shared::cluster.global.mbarrier::complete_tx::bytes "
        "[%0], [%1], %2, [%3];"
        :: "r"(dst_smem), "l"(src), "r"((uint32_t)STAGE_BYTES), "r"(mb)
        : "memory");
}

__global__ __launch_bounds__(THREADS, 1)
void bitdense_kernel(const uint32_t* __restrict__ inp,
                     const char*     __restrict__ w,
                     const int*      __restrict__ b,
                     float*          __restrict__ out)
{
    extern __shared__ __align__(128) char smem[];
    uint4* s_in  = (uint4*)(smem + SM_IN);
    int*   s_acc = (int*)  (smem + SM_ACC);   // [(st*8+row)*4 + seg]
    int*   s_b   = (int*)  (smem + SM_B);

    const int tid  = threadIdx.x;
    const int warp = tid >> 5;
    const int lane = tid & 31;
    const int row8 = warp & 7;     // row within a stage (0..7)
    const int seg  = warp >> 3;    // 1KB segment within the row (0..3)
    const int bid  = blockIdx.x;

    // CTA's words: bid, bid+GRID, ...  (6 or 7 words)
    const int nwords  = (bid < OUT_WORDS) ? ((OUT_WORDS - 1 - bid) / GRID + 1) : 0;
    const int nstages = nwords * STAGES_PER_WORD;

    // Stage the 4 KB input + prefetch all biases for this CTA's words.
    if (tid < 256) s_in[tid] = ((const uint4*)inp)[tid];
    if (tid < nwords * 32) {
        int k = tid >> 5;
        s_b[tid] = b[(bid + k * GRID) * 32 + (tid & 31)];
    }

    const uint32_t mbar0 = s2u(smem + SM_MBAR);
    if (tid == 0) {
        #pragma unroll
        for (int i = 0; i < DEPTH; i++)
            asm volatile("mbarrier.init.shared.b64 [%0], 1;"
                         :: "r"(mbar0 + 8 * i) : "memory");
    }
    __syncthreads();

    if (nstages == 0) return;

    // Each thread's fixed 32B input slice: conflict-free 16B stride.
    const uint4 in0 = s_in[seg * 64 + lane];        // bytes seg*1024 + lane*16
    const uint4 in1 = s_in[seg * 64 + 32 + lane];   // bytes seg*1024 + 512 + lane*16

    const uint32_t stage_base = s2u(smem + SM_STAGES);

    // Prologue: fill the pipeline.
    if (tid == 0) {
        for (int s = 0; s < DEPTH && s < nstages; s++) {
            int kk = s / STAGES_PER_WORD, st = s % STAGES_PER_WORD;
            const char* src = w + ((size_t)(bid + kk * GRID) * 32 + st * 8) * ROW_BYTES;
            issue_stage(stage_base + (uint32_t)s * STAGE_BYTES, src, mbar0 + 8 * s);
        }
    }

    for (int s = 0; s < nstages; s++) {
        const int buf = s & (DEPTH - 1);
        const uint32_t mb = mbar0 + 8 * buf;
        mbar_wait(mb, (uint32_t)((s / DEPTH) & 1));

        // Consume: this thread reads 2x16B of its (row,seg) slice.
        const uint4* wp = (const uint4*)(smem + SM_STAGES + buf * STAGE_BYTES
                                         + row8 * ROW_BYTES + seg * 1024 + lane * 16);
        uint4 a0 = wp[0];
        uint4 a1 = wp[32];   // +512 bytes
        int acc = __popc(a0.x ^ in0.x) + __popc(a0.y ^ in0.y)
                + __popc(a0.z ^ in0.z) + __popc(a0.w ^ in0.w)
                + __popc(a1.x ^ in1.x) + __popc(a1.y ^ in1.y)
                + __popc(a1.z ^ in1.z) + __popc(a1.w ^ in1.w);
        int sum = __reduce_add_sync(0xffffffffu, acc);

        const int st = s % STAGES_PER_WORD;
        if (lane == 0) s_acc[(st * 8 + row8) * 4 + seg] = sum;
        __syncthreads();   // all reads of 'buf' + acc writes done

        // Refill this buffer for stage s+DEPTH.
        if (tid == 0 && s + DEPTH < nstages) {
            int s2 = s + DEPTH;
            int kk = s2 / STAGES_PER_WORD, st2 = s2 % STAGES_PER_WORD;
            const char* src = w + ((size_t)(bid + kk * GRID) * 32 + st2 * 8) * ROW_BYTES;
            issue_stage(stage_base + (uint32_t)buf * STAGE_BYTES, src, mb);
        }

        if (st == STAGES_PER_WORD - 1) {
            // Word complete: 32 units' partials in s_acc.
            const int k = s / STAGES_PER_WORD;
            if (warp == 0) {
                int ones = s_acc[lane * 4 + 0] + s_acc[lane * 4 + 1]
                         + s_acc[lane * 4 + 2] + s_acc[lane * 4 + 3];
                int o = 32768 - 2 * ones + s_b[k * 32 + lane];
                int sign = (o < 0) ? 1 : 0;
                // packbits: unit u -> word-bit (u^7); fetch neighbor's sign.
                int sp = __shfl_sync(0xffffffffu, sign, lane ^ 7);
                unsigned bits = __ballot_sync(0xffffffffu, sp);
                if (lane == 0)
                    out[bid + k * GRID] = (float)(int32_t)bits;  // signed value
            }
            __syncthreads();   // protect s_acc before next word's writes
        }
    }
}

// Zero any tail of d_out beyond OUT_WORDS (defensive).
__global__ void tail_zero_kernel(float* __restrict__ out, int begin, int n)
{
    int i = begin + blockIdx.x * blockDim.x + threadIdx.x;
    if (i < n) out[i] = 0.0f;
}

extern "C" void kernel_launch(void* const* d_in, const int* in_sizes, int n_in,
                              void* d_out, int out_size)
{
    // Bind inputs by relative size: largest = w, smallest = inputs, rest = b.
    int iw = 0, ii = 0;
    for (int i = 1; i < n_in; i++) {
        if (in_sizes[i] > in_sizes[iw]) iw = i;
        if (in_sizes[i] < in_sizes[ii]) ii = i;
    }
    int ib = 0;
    for (int i = 0; i < n_in; i++) if (i != iw && i != ii) { ib = i; break; }

    const uint32_t* inp = (const uint32_t*)d_in[ii];
    const char*     w   = (const char*)    d_in[iw];
    const int*      b   = (const int*)     d_in[ib];
    float*          out = (float*)         d_out;

    static int configured = 0;
    if (!configured) {
        cudaFuncSetAttribute(bitdense_kernel,
                             cudaFuncAttributeMaxDynamicSharedMemorySize,
                             SMEM_TOTAL);
        configured = 1;
    }

    bitdense_kernel<<<GRID, THREADS, SMEM_TOTAL>>>(inp, w, b, out);

    if (out_size > OUT_WORDS) {
        int tail = out_size - OUT_WORDS;
        tail_zero_kernel<<<(tail + 255) / 256, 256>>>(out, OUT_WORDS, out_size);
    }
}